// round 2
// baseline (speedup 1.0000x reference)
#include <cuda_runtime.h>
#include <math.h>
#include <stdint.h>

#define B_ 2
#define C_ 96
#define D_ 8
#define H_ 48
#define W_ 48
#define L_ (D_*H_*W_)          // 18432
#define NROWS (B_*L_)          // 36864
#define DSTATE 16
#define DINNER 192
#define DTRANK 6
#define NC 72                  // scan chunks
#define CS (L_/NC)             // 256 steps per chunk

// ---------------- scratch (static device globals; allocation-free) ----------------
__device__ float g_h1[B_*C_*L_];            // dwconv out / gn out   (b,c,l)
__device__ float g_h2[B_*4*C_*L_];          // pw1 out               (b,o,l)
__device__ float g_xflat[NROWS*C_];         // x transposed          (row,c)
__device__ float g_xn[NROWS*C_];            // LN(x)                 (row,c)
__device__ float g_xz[NROWS*2*DINNER];      // in_proj out           (row,384)
__device__ float g_u[NROWS*DINNER];         // silu(conv1d)          (row,192)
__device__ float g_xdbl[NROWS*38];          // x_proj out            (row,38)
__device__ float g_dt[NROWS*DINNER];        // softplus dt           (row,192)
__device__ float g_y[NROWS*DINNER];         // scan out gated        (row,192)
__device__ float g_outm[NROWS*C_];          // out_proj out          (row,96)
__device__ float g_xm2[NROWS*C_];           // LN2 out               (row,96)
__device__ float g_stats[32];               // groupnorm sums
__device__ float g_P[NC*384*DSTATE];        // chunk decay products
__device__ float g_F[NC*384*DSTATE];        // chunk zero-state finals
__device__ float g_Hi[NC*384*DSTATE];       // chunk initial states

__device__ __forceinline__ float siluf(float x) { return x / (1.f + __expf(-x)); }

// ---------------- depthwise conv3d (3x7x7, pad 1/3/3) + bias ----------------
__global__ __launch_bounds__(256) void dwconv3d_kernel(const float* __restrict__ x,
                                                       const float* __restrict__ w,
                                                       const float* __restrict__ bias) {
    __shared__ float s[10][22][22];
    __shared__ float wsm[147];
    int bc = blockIdx.z;                 // b*C + c
    int c = bc % C_;
    int h0 = blockIdx.y * 16, w0 = blockIdx.x * 16;
    int tid = threadIdx.y * 16 + threadIdx.x;
    const float* xp = x + (size_t)bc * L_;
    for (int i = tid; i < 147; i += 256) wsm[i] = w[c*147 + i];
    for (int i = tid; i < 10*22*22; i += 256) {
        int dd = i / 484; int r = i % 484; int hh = r / 22; int ww = r % 22;
        int d = dd - 1, h = h0 + hh - 3, wq = w0 + ww - 3;
        float v = 0.f;
        if (d >= 0 && d < D_ && h >= 0 && h < H_ && wq >= 0 && wq < W_)
            v = xp[(d*H_ + h)*W_ + wq];
        s[dd][hh][ww] = v;
    }
    __syncthreads();
    int ty = threadIdx.y, tx = threadIdx.x;
    float bv = bias[c];
    float acc[8];
    #pragma unroll
    for (int i = 0; i < 8; i++) acc[i] = bv;
    #pragma unroll
    for (int dd = 0; dd < 10; dd++) {
        #pragma unroll
        for (int kh = 0; kh < 7; kh++) {
            #pragma unroll
            for (int kw = 0; kw < 7; kw++) {
                float v = s[dd][ty+kh][tx+kw];
                #pragma unroll
                for (int kd = 0; kd < 3; kd++) {
                    int od = dd - kd;
                    if (od >= 0 && od < 8)
                        acc[od] += v * wsm[kd*49 + kh*7 + kw];
                }
            }
        }
    }
    size_t base = (size_t)bc * L_;
    #pragma unroll
    for (int od = 0; od < 8; od++)
        g_h1[base + (od*H_ + h0 + ty)*W_ + (w0 + tx)] = acc[od];
}

// ---------------- groupnorm (8 groups) ----------------
__global__ void zero_stats_kernel() { if (threadIdx.x < 32) g_stats[threadIdx.x] = 0.f; }

__global__ __launch_bounds__(256) void gn_stats_kernel() {
    int z = blockIdx.y;                  // b*8+g
    size_t base = (size_t)((z/8)*C_ + (z%8)*12) * L_;
    int tid = threadIdx.x;
    size_t off = base + (size_t)blockIdx.x * 2048 + tid;
    float s = 0.f, s2 = 0.f;
    #pragma unroll
    for (int i = 0; i < 8; i++) { float v = g_h1[off + (size_t)i*256]; s += v; s2 += v*v; }
    __shared__ float rs[256], rs2[256];
    rs[tid] = s; rs2[tid] = s2; __syncthreads();
    for (int k = 128; k > 0; k >>= 1) {
        if (tid < k) { rs[tid] += rs[tid+k]; rs2[tid] += rs2[tid+k]; }
        __syncthreads();
    }
    if (tid == 0) { atomicAdd(&g_stats[z*2], rs[0]); atomicAdd(&g_stats[z*2+1], rs2[0]); }
}

__global__ __launch_bounds__(256) void gn_norm_kernel(const float* __restrict__ gg,
                                                      const float* __restrict__ gb) {
    size_t idx = (size_t)blockIdx.x * 256 + threadIdx.x;
    if (idx >= (size_t)B_*C_*L_) return;
    int c = (int)((idx / L_) % C_);
    int b = (int)(idx / ((size_t)C_*L_));
    int z = b*8 + c/12;
    float cnt = 12.f * (float)L_;
    float mu = g_stats[z*2] / cnt;
    float var = g_stats[z*2+1] / cnt - mu*mu;
    float inv = rsqrtf(var + 1e-5f);
    g_h1[idx] = (g_h1[idx] - mu) * inv * gg[c] + gb[c];
}

// ---------------- generic tiled SGEMM:  C = act(A @ W^T + bias) ----------------
// A_KM : A stored [K, M] (k-major rows), else [M, K] row-major
// OUT_NM: C stored [N, M], else [M, N]
// ACT: 0 none, 1 exact gelu
// ACC: += into C
template<bool A_KM, bool OUT_NM, int ACT, bool ACC>
__global__ __launch_bounds__(256) void gemm_kernel(
    const float* __restrict__ A, const float* __restrict__ Wt,
    const float* __restrict__ bias, float* __restrict__ Co,
    int M, int N, int K, size_t aBatch, size_t cBatch)
{
    __shared__ float As[16][136];
    __shared__ float Ws[128][17];
    int m0 = blockIdx.x * 128, n0 = blockIdx.y * 128;
    A  += (size_t)blockIdx.z * aBatch;
    Co += (size_t)blockIdx.z * cBatch;
    int tid = threadIdx.x;
    int tm, tn;
    if (OUT_NM) { tm = tid & 15; tn = tid >> 4; }
    else        { tn = tid & 15; tm = tid >> 4; }
    float acc[8][8];
    #pragma unroll
    for (int i = 0; i < 8; i++)
        #pragma unroll
        for (int j = 0; j < 8; j++) acc[i][j] = 0.f;

    for (int k0 = 0; k0 < K; k0 += 16) {
        if (A_KM) {
            #pragma unroll
            for (int i = 0; i < 8; i++) {
                int idx = tid + i*256;
                int kk = idx >> 7, mm = idx & 127;
                As[kk][mm] = A[(size_t)(k0+kk)*M + m0 + mm];
            }
        } else {
            #pragma unroll
            for (int i = 0; i < 8; i++) {
                int idx = tid + i*256;
                int kk = idx & 15, mm = idx >> 4;
                As[kk][mm] = A[(size_t)(m0+mm)*K + k0 + kk];
            }
        }
        #pragma unroll
        for (int i = 0; i < 8; i++) {
            int idx = tid + i*256;
            int kk = idx & 15, nn = idx >> 4;
            Ws[nn][kk] = (n0+nn < N) ? Wt[(size_t)(n0+nn)*K + k0 + kk] : 0.f;
        }
        __syncthreads();
        #pragma unroll
        for (int kk = 0; kk < 16; kk++) {
            float a[8], w[8];
            #pragma unroll
            for (int i = 0; i < 8; i++) a[i] = As[kk][tm + 16*i];
            #pragma unroll
            for (int j = 0; j < 8; j++) w[j] = Ws[tn + 16*j][kk];
            #pragma unroll
            for (int i = 0; i < 8; i++)
                #pragma unroll
                for (int j = 0; j < 8; j++)
                    acc[i][j] = fmaf(a[i], w[j], acc[i][j]);
        }
        __syncthreads();
    }
    #pragma unroll
    for (int j = 0; j < 8; j++) {
        int n = n0 + tn + 16*j;
        if (n < N) {
            float bv = bias ? bias[n] : 0.f;
            #pragma unroll
            for (int i = 0; i < 8; i++) {
                int m = m0 + tm + 16*i;
                float v = acc[i][j] + bv;
                if (ACT == 1) v = 0.5f * v * (1.f + erff(v * 0.70710678118654752f));
                size_t o = OUT_NM ? ((size_t)n*M + m) : ((size_t)m*N + n);
                if (ACC) Co[o] += v; else Co[o] = v;
            }
        }
    }
}

// ---------------- LayerNorm over C with transpose (x (b,c,l) -> rows (b*l, c)) ----------------
__global__ __launch_bounds__(256) void ln1_kernel(const float* __restrict__ x,
                                                  const float* __restrict__ g,
                                                  const float* __restrict__ bta) {
    __shared__ float s[96][33];
    __shared__ float mu_s[32], rs_s[32];
    int b = blockIdx.y;
    int l0 = blockIdx.x * 32;
    int tid = threadIdx.x;
    int tx = tid & 31, ty = tid >> 5;    // 8 rows of ty
    const float* xp = x + (size_t)b * C_ * L_;
    for (int c = ty; c < C_; c += 8)
        s[c][tx] = xp[(size_t)c * L_ + l0 + tx];
    __syncthreads();
    if (tid < 32) {
        float sum = 0.f, sq = 0.f;
        #pragma unroll 4
        for (int c = 0; c < C_; c++) { float v = s[c][tid]; sum += v; sq += v*v; }
        float mu = sum / 96.f;
        float var = sq / 96.f - mu*mu;
        mu_s[tid] = mu; rs_s[tid] = rsqrtf(var + 1e-5f);
    }
    __syncthreads();
    for (int idx = tid; idx < 96*32; idx += 256) {
        int c = idx % 96, l = idx / 96;
        float v = s[c][l];
        size_t row = (size_t)(b*L_ + l0 + l);
        g_xflat[row*96 + c] = v;
        g_xn[row*96 + c] = (v - mu_s[l]) * rs_s[l] * g[c] + bta[c];
    }
}

// ---------------- causal depthwise conv1d (k=4) + SiLU ----------------
__global__ __launch_bounds__(256) void conv1d_kernel(const float* __restrict__ w,
                                                     const float* __restrict__ bias) {
    size_t idx = (size_t)blockIdx.x * 256 + threadIdx.x;
    if (idx >= (size_t)NROWS * DINNER) return;
    int d = (int)(idx % DINNER);
    size_t row = idx / DINNER;
    int l = (int)(row % L_);
    float acc = bias[d];
    #pragma unroll
    for (int k = 0; k < 4; k++) {
        int l2 = l - 3 + k;
        if (l2 >= 0)
            acc += g_xz[(row - (size_t)(3-k)) * 384 + d] * w[d*4 + k];
    }
    g_u[row*DINNER + d] = siluf(acc);
}

// ---------------- dt = softplus(x_dbl[:, :6] @ dt_proj_w^T + b) ----------------
__global__ __launch_bounds__(256) void dt_kernel(const float* __restrict__ dtw,
                                                 const float* __restrict__ dtb) {
    size_t idx = (size_t)blockIdx.x * 256 + threadIdx.x;
    if (idx >= (size_t)NROWS * DINNER) return;
    int d = (int)(idx % DINNER);
    size_t row = idx / DINNER;
    float acc = dtb[d];
    #pragma unroll
    for (int r = 0; r < 6; r++) acc += g_xdbl[row*38 + r] * dtw[d*6 + r];
    g_dt[idx] = (acc > 20.f) ? acc : log1pf(expf(acc));
}

// ---------------- chunked selective scan ----------------
// warp layout: lanes 0-15 = states of channel chan0, lanes 16-31 = chan0+1
__global__ __launch_bounds__(128) void scan_phase1(const float* __restrict__ A_log) {
    int wid = (blockIdx.x * blockDim.x + threadIdx.x) >> 5;
    int lane = threadIdx.x & 31;
    int s = lane & 15, grp = lane >> 4;
    int chunk = wid % NC;
    int pair = wid / NC;                 // 0..191
    int chan = pair*2 + grp;             // 0..383
    int b = chan / DINNER, d = chan % DINNER;
    float Aa = -expf(A_log[d*DSTATE + s]);
    float h = 0.f, P = 1.f;
    size_t l0 = (size_t)b * L_ + (size_t)chunk * CS;
    const float* dtp = g_dt + l0*DINNER + d;
    const float* up  = g_u  + l0*DINNER + d;
    const float* bp  = g_xdbl + l0*38 + 6 + s;
    #pragma unroll 4
    for (int l = 0; l < CS; l++) {
        float dtv = dtp[l*DINNER];
        float uv  = up[l*DINNER];
        float bv  = bp[l*38];
        float a = __expf(dtv * Aa);
        h = a*h + (dtv*uv)*bv;
        P *= a;
    }
    int o = (chunk*384 + chan)*DSTATE + s;
    g_F[o] = h; g_P[o] = P;
}

__global__ __launch_bounds__(256) void scan_phase2() {
    int t = blockIdx.x * 256 + threadIdx.x;      // (chan, s)
    if (t >= 384*DSTATE) return;
    float H = 0.f;
    for (int j = 0; j < NC; j++) {
        int o = j*384*DSTATE + t;
        g_Hi[o] = H;
        H = g_F[o] + g_P[o]*H;
    }
}

__global__ __launch_bounds__(128) void scan_phase3(const float* __restrict__ A_log,
                                                   const float* __restrict__ Dp) {
    int wid = (blockIdx.x * blockDim.x + threadIdx.x) >> 5;
    int lane = threadIdx.x & 31;
    int s = lane & 15, grp = lane >> 4;
    int chunk = wid % NC;
    int pair = wid / NC;
    int chan = pair*2 + grp;
    int b = chan / DINNER, d = chan % DINNER;
    float Aa = -expf(A_log[d*DSTATE + s]);
    float Dpd = Dp[d];
    float h = g_Hi[(chunk*384 + chan)*DSTATE + s];
    size_t l0 = (size_t)b * L_ + (size_t)chunk * CS;
    const float* dtp = g_dt + l0*DINNER + d;
    const float* up  = g_u  + l0*DINNER + d;
    const float* bp  = g_xdbl + l0*38 + 6 + s;
    const float* cp  = g_xdbl + l0*38 + 22 + s;
    const float* zp  = g_xz + l0*384 + 192 + d;
    float* yp = g_y + l0*DINNER + d;
    #pragma unroll 2
    for (int l = 0; l < CS; l++) {
        float dtv = dtp[l*DINNER];
        float uv  = up[l*DINNER];
        float bv  = bp[l*38];
        float cv  = cp[l*38];
        float a = __expf(dtv * Aa);
        h = a*h + (dtv*uv)*bv;
        float p = h * cv;
        p += __shfl_xor_sync(0xffffffffu, p, 8);
        p += __shfl_xor_sync(0xffffffffu, p, 4);
        p += __shfl_xor_sync(0xffffffffu, p, 2);
        p += __shfl_xor_sync(0xffffffffu, p, 1);
        if (s == 0) {
            float zv = zp[l*384];
            yp[l*DINNER] = (p + uv*Dpd) * siluf(zv);
        }
    }
}

// ---------------- residual + LayerNorm (warp per row) ----------------
__global__ __launch_bounds__(256) void ln2_kernel(const float* __restrict__ g,
                                                  const float* __restrict__ bta,
                                                  const float* __restrict__ skip) {
    int warp = (int)((blockIdx.x * blockDim.x + threadIdx.x) >> 5);
    int lane = threadIdx.x & 31;
    if (warp >= NROWS) return;
    float sk = skip[0];
    size_t base = (size_t)warp * 96;
    float t[3]; float sum = 0.f, sq = 0.f;
    #pragma unroll
    for (int i = 0; i < 3; i++) {
        int c = lane + 32*i;
        t[i] = g_outm[base+c] + sk * g_xflat[base+c];
        sum += t[i]; sq += t[i]*t[i];
    }
    #pragma unroll
    for (int k = 16; k > 0; k >>= 1) {
        sum += __shfl_xor_sync(0xffffffffu, sum, k);
        sq  += __shfl_xor_sync(0xffffffffu, sq,  k);
    }
    float mu = sum / 96.f;
    float var = sq / 96.f - mu*mu;
    float inv = rsqrtf(var + 1e-5f);
    #pragma unroll
    for (int i = 0; i < 3; i++) {
        int c = lane + 32*i;
        g_xm2[base+c] = (t[i] - mu) * inv * g[c] + bta[c];
    }
}

// ---------------- launch ----------------
extern "C" void kernel_launch(void* const* d_in, const int* in_sizes, int n_in,
                              void* d_out, int out_size) {
    const float* x     = (const float*)d_in[0];
    const float* dw_w  = (const float*)d_in[1];
    const float* dw_b  = (const float*)d_in[2];
    const float* gn_g  = (const float*)d_in[3];
    const float* gn_b  = (const float*)d_in[4];
    const float* pw1_w = (const float*)d_in[5];
    const float* pw1_b = (const float*)d_in[6];
    const float* pw2_w = (const float*)d_in[7];
    const float* pw2_b = (const float*)d_in[8];
    const float* ln_g  = (const float*)d_in[9];
    const float* ln_b  = (const float*)d_in[10];
    const float* skip  = (const float*)d_in[11];
    const float* inpw  = (const float*)d_in[12];
    const float* c1w   = (const float*)d_in[13];
    const float* c1b   = (const float*)d_in[14];
    const float* xpw   = (const float*)d_in[15];
    const float* dtw   = (const float*)d_in[16];
    const float* dtb   = (const float*)d_in[17];
    const float* A_log = (const float*)d_in[18];
    const float* Dp    = (const float*)d_in[19];
    const float* outpw = (const float*)d_in[20];
    const float* projw = (const float*)d_in[21];
    const float* projb = (const float*)d_in[22];
    float* out = (float*)d_out;

    float *p_h1, *p_h2, *p_xn, *p_xz, *p_u, *p_xdbl, *p_y, *p_outm, *p_xm2;
    cudaGetSymbolAddress((void**)&p_h1,   g_h1);
    cudaGetSymbolAddress((void**)&p_h2,   g_h2);
    cudaGetSymbolAddress((void**)&p_xn,   g_xn);
    cudaGetSymbolAddress((void**)&p_xz,   g_xz);
    cudaGetSymbolAddress((void**)&p_u,    g_u);
    cudaGetSymbolAddress((void**)&p_xdbl, g_xdbl);
    cudaGetSymbolAddress((void**)&p_y,    g_y);
    cudaGetSymbolAddress((void**)&p_outm, g_outm);
    cudaGetSymbolAddress((void**)&p_xm2,  g_xm2);

    // ---- conv branch ----
    dwconv3d_kernel<<<dim3(3,3,B_*C_), dim3(16,16)>>>(x, dw_w, dw_b);
    zero_stats_kernel<<<1,32>>>();
    gn_stats_kernel<<<dim3(108,16),256>>>();
    gn_norm_kernel<<<(B_*C_*L_+255)/256,256>>>(gn_g, gn_b);
    // pw1: h2(b,o,l) = gelu(W1 @ h1), A [K=96, M=L] per batch
    gemm_kernel<true,true,1,false><<<dim3(L_/128, 3, B_),256>>>(
        p_h1, pw1_w, pw1_b, p_h2, L_, 4*C_, C_, (size_t)C_*L_, (size_t)4*C_*L_);
    // pw2: out(b,c,l) = W2 @ h2  -> writes conv_out directly into d_out
    gemm_kernel<true,true,0,false><<<dim3(L_/128, 1, B_),256>>>(
        p_h2, pw2_w, pw2_b, out, L_, C_, 4*C_, (size_t)4*C_*L_, (size_t)C_*L_);

    // ---- mamba branch ----
    ln1_kernel<<<dim3(L_/32, B_),256>>>(x, ln_g, ln_b);
    gemm_kernel<false,false,0,false><<<dim3(NROWS/128, 3, 1),256>>>(
        p_xn, inpw, nullptr, p_xz, NROWS, 2*DINNER, C_, 0, 0);
    conv1d_kernel<<<(NROWS*DINNER)/256,256>>>(c1w, c1b);
    gemm_kernel<false,false,0,false><<<dim3(NROWS/128, 1, 1),256>>>(
        p_u, xpw, nullptr, p_xdbl, NROWS, 38, DINNER, 0, 0);
    dt_kernel<<<(NROWS*DINNER)/256,256>>>(dtw, dtb);
    scan_phase1<<<(192*NC)/4, 128>>>(A_log);
    scan_phase2<<<24,256>>>();
    scan_phase3<<<(192*NC)/4, 128>>>(A_log, Dp);
    gemm_kernel<false,false,0,false><<<dim3(NROWS/128, 1, 1),256>>>(
        p_y, outpw, nullptr, p_outm, NROWS, C_, DINNER, 0, 0);
    ln2_kernel<<<NROWS/8,256>>>(ln_g, ln_b, skip);
    // final proj, transposed write, accumulate onto conv_out in d_out
    gemm_kernel<false,true,0,true><<<dim3(L_/128, 1, B_),256>>>(
        p_xm2, projw, projb, out, L_, C_, C_, (size_t)L_*C_, (size_t)C_*L_);
}

// round 3
// speedup vs baseline: 1.1117x; 1.1117x over previous
#include <cuda_runtime.h>
#include <math.h>
#include <stdint.h>

#define B_ 2
#define C_ 96
#define D_ 8
#define H_ 48
#define W_ 48
#define L_ (D_*H_*W_)          // 18432
#define NROWS (B_*L_)          // 36864
#define DSTATE 16
#define DINNER 192
#define DTRANK 6
#define NC 72                  // scan chunks
#define CS (L_/NC)             // 256 steps per chunk

// ---------------- scratch (static device globals; allocation-free) ----------------
__device__ float g_h1[B_*C_*L_];            // dwconv out / gn out   (b,c,l)
__device__ float g_h2[B_*4*C_*L_];          // pw1 out               (b,o,l)
__device__ float g_xflat[NROWS*C_];         // x transposed          (row,c)
__device__ float g_xn[NROWS*C_];            // LN(x)                 (row,c)
__device__ float g_xz[NROWS*2*DINNER];      // in_proj out           (row,384)
__device__ float g_u[NROWS*DINNER];         // silu(conv1d)          (row,192)
__device__ float g_xdbl[NROWS*38];          // x_proj out            (row,38)
__device__ float g_dt[NROWS*DINNER];        // softplus dt           (row,192)
__device__ float g_y[NROWS*DINNER];         // scan out gated        (row,192)
__device__ float g_outm[NROWS*C_];          // out_proj out          (row,96)
__device__ float g_xm2[NROWS*C_];           // LN2 out               (row,96)
__device__ float g_stats[32];               // groupnorm sums
__device__ float g_P[NC*384*DSTATE];        // chunk decay products
__device__ float g_F[NC*384*DSTATE];        // chunk zero-state finals
__device__ float g_Hi[NC*384*DSTATE];       // chunk initial states

__device__ __forceinline__ float siluf(float x) { return x / (1.f + __expf(-x)); }
__device__ __forceinline__ float geluf(float x) {
    return 0.5f * x * (1.f + erff(x * 0.70710678118654752f));
}

// f32x2 packed helpers (sm_100a)
__device__ __forceinline__ unsigned long long packbc(float x) {
    unsigned long long r;
    asm("mov.b64 %0, {%1, %1};" : "=l"(r) : "f"(x));
    return r;
}
__device__ __forceinline__ float2 unpack2(unsigned long long v) {
    float2 r;
    asm("mov.b64 {%0, %1}, %2;" : "=f"(r.x), "=f"(r.y) : "l"(v));
    return r;
}
#define FMA2(d, a, b) asm("fma.rn.f32x2 %0, %1, %2, %0;" : "+l"(d) : "l"(a), "l"(b))

// ---------------- depthwise conv3d (3x7x7, pad 1/3/3) + bias ----------------
__global__ __launch_bounds__(256) void dwconv3d_kernel(const float* __restrict__ x,
                                                       const float* __restrict__ w,
                                                       const float* __restrict__ bias) {
    __shared__ float s[10][22][22];
    __shared__ float wsm[147];
    int bc = blockIdx.z;                 // b*C + c
    int c = bc % C_;
    int h0 = blockIdx.y * 16, w0 = blockIdx.x * 16;
    int tid = threadIdx.y * 16 + threadIdx.x;
    const float* xp = x + (size_t)bc * L_;
    for (int i = tid; i < 147; i += 256) wsm[i] = w[c*147 + i];
    for (int i = tid; i < 10*22*22; i += 256) {
        int dd = i / 484; int r = i % 484; int hh = r / 22; int ww = r % 22;
        int d = dd - 1, h = h0 + hh - 3, wq = w0 + ww - 3;
        float v = 0.f;
        if (d >= 0 && d < D_ && h >= 0 && h < H_ && wq >= 0 && wq < W_)
            v = xp[(d*H_ + h)*W_ + wq];
        s[dd][hh][ww] = v;
    }
    __syncthreads();
    int ty = threadIdx.y, tx = threadIdx.x;
    float bv = bias[c];
    float acc[8];
    #pragma unroll
    for (int i = 0; i < 8; i++) acc[i] = bv;
    #pragma unroll
    for (int dd = 0; dd < 10; dd++) {
        #pragma unroll
        for (int kh = 0; kh < 7; kh++) {
            #pragma unroll
            for (int kw = 0; kw < 7; kw++) {
                float v = s[dd][ty+kh][tx+kw];
                #pragma unroll
                for (int kd = 0; kd < 3; kd++) {
                    int od = dd - kd;
                    if (od >= 0 && od < 8)
                        acc[od] += v * wsm[kd*49 + kh*7 + kw];
                }
            }
        }
    }
    size_t base = (size_t)bc * L_;
    #pragma unroll
    for (int od = 0; od < 8; od++)
        g_h1[base + (od*H_ + h0 + ty)*W_ + (w0 + tx)] = acc[od];
}

// ---------------- groupnorm (8 groups) ----------------
__global__ void zero_stats_kernel() { if (threadIdx.x < 32) g_stats[threadIdx.x] = 0.f; }

__global__ __launch_bounds__(256) void gn_stats_kernel() {
    int z = blockIdx.y;                  // b*8+g
    size_t base = (size_t)((z/8)*C_ + (z%8)*12) * L_;
    int tid = threadIdx.x;
    size_t off = base + (size_t)blockIdx.x * 2048 + tid;
    float s = 0.f, s2 = 0.f;
    #pragma unroll
    for (int i = 0; i < 8; i++) { float v = g_h1[off + (size_t)i*256]; s += v; s2 += v*v; }
    __shared__ float rs[256], rs2[256];
    rs[tid] = s; rs2[tid] = s2; __syncthreads();
    for (int k = 128; k > 0; k >>= 1) {
        if (tid < k) { rs[tid] += rs[tid+k]; rs2[tid] += rs2[tid+k]; }
        __syncthreads();
    }
    if (tid == 0) { atomicAdd(&g_stats[z*2], rs[0]); atomicAdd(&g_stats[z*2+1], rs2[0]); }
}

__global__ __launch_bounds__(256) void gn_norm_kernel(const float* __restrict__ gg,
                                                      const float* __restrict__ gb) {
    int c = blockIdx.y, b = blockIdx.z;
    size_t idx = ((size_t)b*C_ + c) * L_ + (size_t)blockIdx.x * 256 + threadIdx.x;
    int z = b*8 + c/12;
    float cnt = 12.f * (float)L_;
    float mu = g_stats[z*2] / cnt;
    float var = g_stats[z*2+1] / cnt - mu*mu;
    float inv = rsqrtf(var + 1e-5f);
    g_h1[idx] = (g_h1[idx] - mu) * inv * gg[c] + gb[c];
}

// ---------------- GEMM v2: f32x2, 128 threads, BM=128, 16 rows x (4*NH) cols/thread ----
// A_KM : A stored [K, M]; else [M, K]
// OUT_NM: C stored [N, M]; else [M, N]
// ACT: 0 none, 1 exact gelu ; ACC: += into C
template<bool A_KM, bool OUT_NM, int ACT, bool ACC, int BN>
__global__ __launch_bounds__(128) void gemm2_kernel(
    const float* __restrict__ A, const float* __restrict__ Wt,
    const float* __restrict__ bias, float* __restrict__ Co,
    int M, int N, int K, size_t aBatch, size_t cBatch)
{
    constexpr int NH = BN / 64;          // 2 or 1
    constexpr int NCOL = NH * 4;         // 8 or 4
    __shared__ float As[16][132];
    __shared__ float Ws[16][BN + 4];
    int m0 = blockIdx.x * 128, n0 = blockIdx.y * BN;
    A  += (size_t)blockIdx.z * aBatch;
    Co += (size_t)blockIdx.z * cBatch;
    int tid = threadIdx.x;
    int tn = tid & 15;                   // 0..15
    int tm = tid >> 4;                   // 0..7

    unsigned long long acc2[8][NCOL];    // row-pairs x cols
    #pragma unroll
    for (int rp = 0; rp < 8; rp++)
        #pragma unroll
        for (int c = 0; c < NCOL; c++) acc2[rp][c] = 0ull;

    for (int k0 = 0; k0 < K; k0 += 16) {
        // load A tile
        if (A_KM) {
            #pragma unroll
            for (int t = 0; t < 4; t++) {
                int f = tid + t*128;
                int kk = f >> 5; int p4 = (f & 31) << 2;
                float4 v = *(const float4*)(A + (size_t)(k0+kk)*M + m0 + p4);
                *(float4*)&As[kk][p4] = v;
            }
        } else {
            #pragma unroll
            for (int t = 0; t < 4; t++) {
                int f = tid + t*128;
                int mm = f >> 2; int q4 = (f & 3) << 2;
                float4 v = *(const float4*)(A + (size_t)(m0+mm)*K + k0 + q4);
                As[q4+0][mm] = v.x; As[q4+1][mm] = v.y;
                As[q4+2][mm] = v.z; As[q4+3][mm] = v.w;
            }
        }
        // load W tile (guard rows >= N with zeros)
        #pragma unroll
        for (int t = 0; t < NH*2; t++) {
            int f = tid + t*128;
            int nn = f >> 2; int q4 = (f & 3) << 2;
            float4 v = make_float4(0.f, 0.f, 0.f, 0.f);
            if (n0 + nn < N) v = *(const float4*)(Wt + (size_t)(n0+nn)*K + k0 + q4);
            Ws[q4+0][nn] = v.x; Ws[q4+1][nn] = v.y;
            Ws[q4+2][nn] = v.z; Ws[q4+3][nn] = v.w;
        }
        __syncthreads();
        #pragma unroll
        for (int kk = 0; kk < 16; kk++) {
            unsigned long long a2[8];
            #pragma unroll
            for (int g = 0; g < 4; g++) {
                a2[g*2+0] = *(const unsigned long long*)&As[kk][g*32 + tm*4];
                a2[g*2+1] = *(const unsigned long long*)&As[kk][g*32 + tm*4 + 2];
            }
            unsigned long long w2[NCOL];
            #pragma unroll
            for (int h = 0; h < NH; h++) {
                float4 wv = *(const float4*)&Ws[kk][h*64 + tn*4];
                w2[h*4+0] = packbc(wv.x); w2[h*4+1] = packbc(wv.y);
                w2[h*4+2] = packbc(wv.z); w2[h*4+3] = packbc(wv.w);
            }
            #pragma unroll
            for (int rp = 0; rp < 8; rp++)
                #pragma unroll
                for (int c = 0; c < NCOL; c++)
                    FMA2(acc2[rp][c], a2[rp], w2[c]);
        }
        __syncthreads();
    }

    if (OUT_NM) {
        // C[n*M + m], m contiguous per thread group of 4
        #pragma unroll
        for (int h = 0; h < NH; h++)
            #pragma unroll
            for (int j = 0; j < 4; j++) {
                int c = h*4 + j;
                int n = n0 + h*64 + tn*4 + j;
                if (n >= N) continue;
                float bv = bias ? bias[n] : 0.f;
                float* cp = Co + (size_t)n*M + m0;
                #pragma unroll
                for (int g = 0; g < 4; g++) {
                    float2 lo = unpack2(acc2[g*2+0][c]);
                    float2 hi = unpack2(acc2[g*2+1][c]);
                    float4 v;
                    v.x = lo.x + bv; v.y = lo.y + bv;
                    v.z = hi.x + bv; v.w = hi.y + bv;
                    if (ACT == 1) {
                        v.x = geluf(v.x); v.y = geluf(v.y);
                        v.z = geluf(v.z); v.w = geluf(v.w);
                    }
                    float* dst = cp + g*32 + tm*4;
                    if (ACC) {
                        float4 o = *(float4*)dst;
                        v.x += o.x; v.y += o.y; v.z += o.z; v.w += o.w;
                    }
                    *(float4*)dst = v;
                }
            }
    } else {
        // C[m*N + n]
        bool vec = ((N & 3) == 0);
        #pragma unroll
        for (int g = 0; g < 4; g++)
            #pragma unroll
            for (int p = 0; p < 2; p++)
                #pragma unroll
                for (int e = 0; e < 2; e++) {
                    int m = m0 + g*32 + tm*4 + p*2 + e;
                    float* rowp = Co + (size_t)m*N;
                    #pragma unroll
                    for (int h = 0; h < NH; h++) {
                        int nb = n0 + h*64 + tn*4;
                        float vv[4];
                        #pragma unroll
                        for (int j = 0; j < 4; j++) {
                            float2 uv = unpack2(acc2[g*2+p][h*4+j]);
                            float v = (e == 0) ? uv.x : uv.y;
                            if (nb + j < N) v += (bias ? bias[nb+j] : 0.f);
                            if (ACT == 1) v = geluf(v);
                            vv[j] = v;
                        }
                        if (vec && nb + 3 < N) {
                            float4 v4 = make_float4(vv[0], vv[1], vv[2], vv[3]);
                            if (ACC) {
                                float4 o = *(float4*)(rowp + nb);
                                v4.x += o.x; v4.y += o.y; v4.z += o.z; v4.w += o.w;
                            }
                            *(float4*)(rowp + nb) = v4;
                        } else {
                            #pragma unroll
                            for (int j = 0; j < 4; j++) {
                                if (nb + j < N) {
                                    float v = vv[j];
                                    if (ACC) v += rowp[nb+j];
                                    rowp[nb+j] = v;
                                }
                            }
                        }
                    }
                }
    }
}

// ---------------- LayerNorm over C with transpose (x (b,c,l) -> rows (b*l, c)) ----------------
__global__ __launch_bounds__(256) void ln1_kernel(const float* __restrict__ x,
                                                  const float* __restrict__ g,
                                                  const float* __restrict__ bta) {
    __shared__ float s[96][33];
    __shared__ float mu_s[32], rs_s[32];
    int b = blockIdx.y;
    int l0 = blockIdx.x * 32;
    int tid = threadIdx.x;
    int tx = tid & 31, ty = tid >> 5;
    const float* xp = x + (size_t)b * C_ * L_;
    for (int c = ty; c < C_; c += 8)
        s[c][tx] = xp[(size_t)c * L_ + l0 + tx];
    __syncthreads();
    if (tid < 32) {
        float sum = 0.f, sq = 0.f;
        #pragma unroll 4
        for (int c = 0; c < C_; c++) { float v = s[c][tid]; sum += v; sq += v*v; }
        float mu = sum / 96.f;
        float var = sq / 96.f - mu*mu;
        mu_s[tid] = mu; rs_s[tid] = rsqrtf(var + 1e-5f);
    }
    __syncthreads();
    for (int idx = tid; idx < 96*32; idx += 256) {
        int c = idx % 96, l = idx / 96;
        float v = s[c][l];
        size_t row = (size_t)(b*L_ + l0 + l);
        g_xflat[row*96 + c] = v;
        g_xn[row*96 + c] = (v - mu_s[l]) * rs_s[l] * g[c] + bta[c];
    }
}

// ---------------- causal depthwise conv1d (k=4) + SiLU, 4 channels/thread -------------
__global__ __launch_bounds__(256) void conv1d_kernel(const float* __restrict__ w,
                                                     const float* __restrict__ bias) {
    size_t idx = (size_t)blockIdx.x * 256 + threadIdx.x;   // (row, d/4)
    if (idx >= (size_t)NROWS * 48) return;
    int d4 = (int)(idx % 48) * 4;
    size_t row = idx / 48;
    int l = (int)(row % L_);
    // per-channel taps
    float4 w0 = *(const float4*)(w + (d4+0)*4);
    float4 w1 = *(const float4*)(w + (d4+1)*4);
    float4 w2 = *(const float4*)(w + (d4+2)*4);
    float4 w3 = *(const float4*)(w + (d4+3)*4);
    float4 acc = *(const float4*)(bias + d4);
    #pragma unroll
    for (int k = 0; k < 4; k++) {
        if (l - 3 + k >= 0) {
            float4 xv = *(const float4*)(g_xz + (row - (size_t)(3-k)) * 384 + d4);
            acc.x += xv.x * ((&w0.x)[k]);
            acc.y += xv.y * ((&w1.x)[k]);
            acc.z += xv.z * ((&w2.x)[k]);
            acc.w += xv.w * ((&w3.x)[k]);
        }
    }
    acc.x = siluf(acc.x); acc.y = siluf(acc.y);
    acc.z = siluf(acc.z); acc.w = siluf(acc.w);
    *(float4*)(g_u + row*DINNER + d4) = acc;
}

// ---------------- dt = softplus(x_dbl[:, :6] @ dt_proj_w^T + b) ----------------
__global__ __launch_bounds__(256) void dt_kernel(const float* __restrict__ dtw,
                                                 const float* __restrict__ dtb) {
    size_t idx = (size_t)blockIdx.x * 256 + threadIdx.x;
    if (idx >= (size_t)NROWS * DINNER) return;
    int d = (int)(idx % DINNER);
    size_t row = idx / DINNER;
    float acc = dtb[d];
    #pragma unroll
    for (int r = 0; r < 6; r++) acc += g_xdbl[row*38 + r] * dtw[d*6 + r];
    g_dt[idx] = (acc > 20.f) ? acc : log1pf(expf(acc));
}

// ---------------- chunked selective scan ----------------
// warp layout: lanes 0-15 = states of channel chan0, lanes 16-31 = chan0+1
// block of 4 warps shares one chunk (locality for B/C loads)
__global__ __launch_bounds__(128) void scan_phase1(const float* __restrict__ A_log) {
    int wid = (blockIdx.x * blockDim.x + threadIdx.x) >> 5;
    int lane = threadIdx.x & 31;
    int s = lane & 15, grp = lane >> 4;
    int pair = wid % 192;
    int chunk = wid / 192;
    int chan = pair*2 + grp;             // 0..383
    int b = chan / DINNER, d = chan % DINNER;
    float Aa = -expf(A_log[d*DSTATE + s]);
    float h = 0.f, P = 1.f;
    size_t l0 = (size_t)b * L_ + (size_t)chunk * CS;
    const float* dtp = g_dt + l0*DINNER + d;
    const float* up  = g_u  + l0*DINNER + d;
    const float* bp  = g_xdbl + l0*38 + 6 + s;
    #pragma unroll 4
    for (int l = 0; l < CS; l++) {
        float dtv = dtp[l*DINNER];
        float uv  = up[l*DINNER];
        float bv  = bp[l*38];
        float a = __expf(dtv * Aa);
        h = a*h + (dtv*uv)*bv;
        P *= a;
    }
    int o = (chunk*384 + chan)*DSTATE + s;
    g_F[o] = h; g_P[o] = P;
}

__global__ __launch_bounds__(256) void scan_phase2() {
    int t = blockIdx.x * 256 + threadIdx.x;      // (chan, s)
    if (t >= 384*DSTATE) return;
    float H = 0.f;
    for (int j = 0; j < NC; j++) {
        int o = j*384*DSTATE + t;
        g_Hi[o] = H;
        H = g_F[o] + g_P[o]*H;
    }
}

__global__ __launch_bounds__(128) void scan_phase3(const float* __restrict__ A_log,
                                                   const float* __restrict__ Dp) {
    int wid = (blockIdx.x * blockDim.x + threadIdx.x) >> 5;
    int lane = threadIdx.x & 31;
    int s = lane & 15, grp = lane >> 4;
    int pair = wid % 192;
    int chunk = wid / 192;
    int chan = pair*2 + grp;
    int b = chan / DINNER, d = chan % DINNER;
    float Aa = -expf(A_log[d*DSTATE + s]);
    float Dpd = Dp[d];
    float h = g_Hi[(chunk*384 + chan)*DSTATE + s];
    size_t l0 = (size_t)b * L_ + (size_t)chunk * CS;
    const float* dtp = g_dt + l0*DINNER + d;
    const float* up  = g_u  + l0*DINNER + d;
    const float* bp  = g_xdbl + l0*38 + 6 + s;
    const float* cp  = g_xdbl + l0*38 + 22 + s;
    const float* zp  = g_xz + l0*384 + 192 + d;
    float* yp = g_y + l0*DINNER + d;
    #pragma unroll 2
    for (int l = 0; l < CS; l++) {
        float dtv = dtp[l*DINNER];
        float uv  = up[l*DINNER];
        float bv  = bp[l*38];
        float cv  = cp[l*38];
        float a = __expf(dtv * Aa);
        h = a*h + (dtv*uv)*bv;
        float p = h * cv;
        p += __shfl_xor_sync(0xffffffffu, p, 8);
        p += __shfl_xor_sync(0xffffffffu, p, 4);
        p += __shfl_xor_sync(0xffffffffu, p, 2);
        p += __shfl_xor_sync(0xffffffffu, p, 1);
        if (s == 0) {
            float zv = zp[l*384];
            yp[l*DINNER] = (p + uv*Dpd) * siluf(zv);
        }
    }
}

// ---------------- residual + LayerNorm (warp per row) ----------------
__global__ __launch_bounds__(256) void ln2_kernel(const float* __restrict__ g,
                                                  const float* __restrict__ bta,
                                                  const float* __restrict__ skip) {
    int warp = (int)((blockIdx.x * blockDim.x + threadIdx.x) >> 5);
    int lane = threadIdx.x & 31;
    if (warp >= NROWS) return;
    float sk = skip[0];
    size_t base = (size_t)warp * 96;
    float t[3]; float sum = 0.f, sq = 0.f;
    #pragma unroll
    for (int i = 0; i < 3; i++) {
        int c = lane + 32*i;
        t[i] = g_outm[base+c] + sk * g_xflat[base+c];
        sum += t[i]; sq += t[i]*t[i];
    }
    #pragma unroll
    for (int k = 16; k > 0; k >>= 1) {
        sum += __shfl_xor_sync(0xffffffffu, sum, k);
        sq  += __shfl_xor_sync(0xffffffffu, sq,  k);
    }
    float mu = sum / 96.f;
    float var = sq / 96.f - mu*mu;
    float inv = rsqrtf(var + 1e-5f);
    #pragma unroll
    for (int i = 0; i < 3; i++) {
        int c = lane + 32*i;
        g_xm2[base+c] = (t[i] - mu) * inv * g[c] + bta[c];
    }
}

// ---------------- launch ----------------
extern "C" void kernel_launch(void* const* d_in, const int* in_sizes, int n_in,
                              void* d_out, int out_size) {
    const float* x     = (const float*)d_in[0];
    const float* dw_w  = (const float*)d_in[1];
    const float* dw_b  = (const float*)d_in[2];
    const float* gn_g  = (const float*)d_in[3];
    const float* gn_b  = (const float*)d_in[4];
    const float* pw1_w = (const float*)d_in[5];
    const float* pw1_b = (const float*)d_in[6];
    const float* pw2_w = (const float*)d_in[7];
    const float* pw2_b = (const float*)d_in[8];
    const float* ln_g  = (const float*)d_in[9];
    const float* ln_b  = (const float*)d_in[10];
    const float* skip  = (const float*)d_in[11];
    const float* inpw  = (const float*)d_in[12];
    const float* c1w   = (const float*)d_in[13];
    const float* c1b   = (const float*)d_in[14];
    const float* xpw   = (const float*)d_in[15];
    const float* dtw   = (const float*)d_in[16];
    const float* dtb   = (const float*)d_in[17];
    const float* A_log = (const float*)d_in[18];
    const float* Dp    = (const float*)d_in[19];
    const float* outpw = (const float*)d_in[20];
    const float* projw = (const float*)d_in[21];
    const float* projb = (const float*)d_in[22];
    float* out = (float*)d_out;

    float *p_h1, *p_h2, *p_xn, *p_xz, *p_u, *p_xdbl, *p_y, *p_outm, *p_xm2;
    cudaGetSymbolAddress((void**)&p_h1,   g_h1);
    cudaGetSymbolAddress((void**)&p_h2,   g_h2);
    cudaGetSymbolAddress((void**)&p_xn,   g_xn);
    cudaGetSymbolAddress((void**)&p_xz,   g_xz);
    cudaGetSymbolAddress((void**)&p_u,    g_u);
    cudaGetSymbolAddress((void**)&p_xdbl, g_xdbl);
    cudaGetSymbolAddress((void**)&p_y,    g_y);
    cudaGetSymbolAddress((void**)&p_outm, g_outm);
    cudaGetSymbolAddress((void**)&p_xm2,  g_xm2);

    // ---- conv branch ----
    dwconv3d_kernel<<<dim3(3,3,B_*C_), dim3(16,16)>>>(x, dw_w, dw_b);
    zero_stats_kernel<<<1,32>>>();
    gn_stats_kernel<<<dim3(108,16),256>>>();
    gn_norm_kernel<<<dim3(L_/256, C_, B_),256>>>(gn_g, gn_b);
    // pw1: h2(b,o,l) = gelu(W1 @ h1), A [K=96, M=L] per batch
    gemm2_kernel<true,true,1,false,128><<<dim3(L_/128, 3, B_),128>>>(
        p_h1, pw1_w, pw1_b, p_h2, L_, 4*C_, C_, (size_t)C_*L_, (size_t)4*C_*L_);
    // pw2: out(b,c,l) = W2 @ h2  -> writes conv_out directly into d_out
    gemm2_kernel<true,true,0,false,128><<<dim3(L_/128, 1, B_),128>>>(
        p_h2, pw2_w, pw2_b, out, L_, C_, 4*C_, (size_t)4*C_*L_, (size_t)C_*L_);

    // ---- mamba branch ----
    ln1_kernel<<<dim3(L_/32, B_),256>>>(x, ln_g, ln_b);
    gemm2_kernel<false,false,0,false,128><<<dim3(NROWS/128, 3, 1),128>>>(
        p_xn, inpw, nullptr, p_xz, NROWS, 2*DINNER, C_, 0, 0);
    conv1d_kernel<<<(NROWS*48)/256,256>>>(c1w, c1b);
    gemm2_kernel<false,false,0,false,64><<<dim3(NROWS/128, 1, 1),128>>>(
        p_u, xpw, nullptr, p_xdbl, NROWS, 38, DINNER, 0, 0);
    dt_kernel<<<(NROWS*DINNER)/256,256>>>(dtw, dtb);
    scan_phase1<<<(192*NC)/4, 128>>>(A_log);
    scan_phase2<<<24,256>>>();
    scan_phase3<<<(192*NC)/4, 128>>>(A_log, Dp);
    gemm2_kernel<false,false,0,false,128><<<dim3(NROWS/128, 1, 1),128>>>(
        p_y, outpw, nullptr, p_outm, NROWS, C_, DINNER, 0, 0);
    ln2_kernel<<<NROWS/8,256>>>(ln_g, ln_b, skip);
    // final proj, transposed write, accumulate onto conv_out in d_out
    gemm2_kernel<false,true,0,true,128><<<dim3(L_/128, 1, B_),128>>>(
        p_xm2, projw, projb, out, L_, C_, C_, (size_t)L_*C_, (size_t)C_*L_);
}

// round 4
// speedup vs baseline: 1.3348x; 1.2007x over previous
#include <cuda_runtime.h>
#include <math.h>
#include <stdint.h>

#define B_ 2
#define C_ 96
#define D_ 8
#define H_ 48
#define W_ 48
#define L_ (D_*H_*W_)          // 18432
#define NROWS (B_*L_)          // 36864
#define DSTATE 16
#define DINNER 192
#define NC 72                  // scan chunks
#define CS (L_/NC)             // 256 steps per chunk

// ---------------- scratch ----------------
__device__ float g_h1[B_*C_*L_];            // dwconv out (raw, pre-GN)  (b,c,l)
__device__ float g_h2[B_*4*C_*L_];          // pw1 out               (b,o,l)
__device__ float g_xflat[NROWS*C_];         // x transposed          (row,c)
__device__ float g_xn[NROWS*C_];            // LN(x)                 (row,c)
__device__ float g_xzT[2*DINNER*NROWS];     // in_proj out T         [n][row], n<192: xm, n>=192: z
__device__ float g_uT[DINNER*NROWS];        // silu(conv1d) T        [d][row]
__device__ float g_xdT[38*NROWS];           // x_proj out T          [r][row]
__device__ float g_dtT[DINNER*NROWS];       // softplus dt T         [d][row]
__device__ float g_yT[DINNER*NROWS];        // scan out gated T      [d][row]
__device__ float g_outm[NROWS*C_];          // out_proj out          (row,96)
__device__ float g_xm2[NROWS*C_];           // LN2 out               (row,96)
__device__ float g_stats[32];               // groupnorm sums
__device__ float g_gnsc[B_*C_];             // per (b,c) scale
__device__ float g_gnsh[B_*C_];             // per (b,c) shift
__device__ float g_P[NC*384*DSTATE];
__device__ float g_F[NC*384*DSTATE];
__device__ float g_Hi[NC*384*DSTATE];

__device__ __forceinline__ float siluf(float x) { return x / (1.f + __expf(-x)); }
__device__ __forceinline__ float geluf(float x) {
    return 0.5f * x * (1.f + erff(x * 0.70710678118654752f));
}

// f32x2 packed helpers (sm_100a)
__device__ __forceinline__ unsigned long long packbc(float x) {
    unsigned long long r;
    asm("mov.b64 %0, {%1, %1};" : "=l"(r) : "f"(x));
    return r;
}
__device__ __forceinline__ float2 unpack2(unsigned long long v) {
    float2 r;
    asm("mov.b64 {%0, %1}, %2;" : "=f"(r.x), "=f"(r.y) : "l"(v));
    return r;
}
#define FMA2(d, a, b) asm("fma.rn.f32x2 %0, %1, %2, %0;" : "+l"(d) : "l"(a), "l"(b))

// ---------------- depthwise conv3d (3x7x7, pad 1/3/3) + bias + fused GN stats --------
__global__ __launch_bounds__(256) void dwconv3d_kernel(const float* __restrict__ x,
                                                       const float* __restrict__ w,
                                                       const float* __restrict__ bias) {
    __shared__ float s[10][22][22];
    __shared__ float wsm[147];
    __shared__ float r1[8], r2[8];
    int bc = blockIdx.z;                 // b*C + c
    int c = bc % C_;
    int b = bc / C_;
    int h0 = blockIdx.y * 16, w0 = blockIdx.x * 16;
    int tid = threadIdx.y * 16 + threadIdx.x;
    const float* xp = x + (size_t)bc * L_;
    for (int i = tid; i < 147; i += 256) wsm[i] = w[c*147 + i];
    for (int i = tid; i < 10*22*22; i += 256) {
        int dd = i / 484; int r = i % 484; int hh = r / 22; int ww = r % 22;
        int d = dd - 1, h = h0 + hh - 3, wq = w0 + ww - 3;
        float v = 0.f;
        if (d >= 0 && d < D_ && h >= 0 && h < H_ && wq >= 0 && wq < W_)
            v = xp[(d*H_ + h)*W_ + wq];
        s[dd][hh][ww] = v;
    }
    __syncthreads();
    int ty = threadIdx.y, tx = threadIdx.x;
    float bv = bias[c];
    float acc[8];
    #pragma unroll
    for (int i = 0; i < 8; i++) acc[i] = bv;
    #pragma unroll
    for (int dd = 0; dd < 10; dd++) {
        #pragma unroll
        for (int kh = 0; kh < 7; kh++) {
            #pragma unroll
            for (int kw = 0; kw < 7; kw++) {
                float v = s[dd][ty+kh][tx+kw];
                #pragma unroll
                for (int kd = 0; kd < 3; kd++) {
                    int od = dd - kd;
                    if (od >= 0 && od < 8)
                        acc[od] += v * wsm[kd*49 + kh*7 + kw];
                }
            }
        }
    }
    size_t base = (size_t)bc * L_;
    float s1 = 0.f, s2 = 0.f;
    #pragma unroll
    for (int od = 0; od < 8; od++) {
        g_h1[base + (od*H_ + h0 + ty)*W_ + (w0 + tx)] = acc[od];
        s1 += acc[od]; s2 += acc[od]*acc[od];
    }
    // block reduce for GN stats
    #pragma unroll
    for (int k = 16; k > 0; k >>= 1) {
        s1 += __shfl_xor_sync(0xffffffffu, s1, k);
        s2 += __shfl_xor_sync(0xffffffffu, s2, k);
    }
    if ((tid & 31) == 0) { r1[tid >> 5] = s1; r2[tid >> 5] = s2; }
    __syncthreads();
    if (tid == 0) {
        float t1 = 0.f, t2 = 0.f;
        #pragma unroll
        for (int i = 0; i < 8; i++) { t1 += r1[i]; t2 += r2[i]; }
        int z = b*8 + c/12;
        atomicAdd(&g_stats[z*2], t1);
        atomicAdd(&g_stats[z*2+1], t2);
    }
}

__global__ void zero_stats_kernel() { if (threadIdx.x < 32) g_stats[threadIdx.x] = 0.f; }

__global__ void gn_scale_kernel(const float* __restrict__ gg, const float* __restrict__ gb) {
    int i = threadIdx.x;
    if (i >= B_*C_) return;
    int b = i / C_, c = i % C_;
    int z = b*8 + c/12;
    float cnt = 12.f * (float)L_;
    float mu = g_stats[z*2] / cnt;
    float var = g_stats[z*2+1] / cnt - mu*mu;
    float inv = rsqrtf(var + 1e-5f);
    g_gnsc[i] = inv * gg[c];
    g_gnsh[i] = gb[c] - mu * inv * gg[c];
}

// ---------------- GEMM v2: f32x2, 128 threads, BM=128 ----------------
// A_KM : A stored [K, M]; else [M, K]
// OUT_NM: C stored [N, M]; else [M, N]
// ACT: 0 none, 1 exact gelu ; ACC: += into C ; NORM: per-k scale/shift on A (A_KM only)
template<bool A_KM, bool OUT_NM, int ACT, bool ACC, int BN, bool NORM>
__global__ __launch_bounds__(128) void gemm2_kernel(
    const float* __restrict__ A, const float* __restrict__ Wt,
    const float* __restrict__ bias, float* __restrict__ Co,
    int M, int N, int K, size_t aBatch, size_t cBatch,
    const float* __restrict__ nscB, const float* __restrict__ nshB)
{
    constexpr int NH = BN / 64;
    constexpr int NCOL = NH * 4;
    __shared__ float As[16][132];
    __shared__ float Ws[16][BN + 4];
    int m0 = blockIdx.x * 128, n0 = blockIdx.y * BN;
    A  += (size_t)blockIdx.z * aBatch;
    Co += (size_t)blockIdx.z * cBatch;
    const float* nsc = NORM ? (nscB + blockIdx.z * C_) : nullptr;
    const float* nsh = NORM ? (nshB + blockIdx.z * C_) : nullptr;
    int tid = threadIdx.x;
    int tn = tid & 15;
    int tm = tid >> 4;

    unsigned long long acc2[8][NCOL];
    #pragma unroll
    for (int rp = 0; rp < 8; rp++)
        #pragma unroll
        for (int c = 0; c < NCOL; c++) acc2[rp][c] = 0ull;

    for (int k0 = 0; k0 < K; k0 += 16) {
        if (A_KM) {
            #pragma unroll
            for (int t = 0; t < 4; t++) {
                int f = tid + t*128;
                int kk = f >> 5; int p4 = (f & 31) << 2;
                float4 v = *(const float4*)(A + (size_t)(k0+kk)*M + m0 + p4);
                if (NORM) {
                    float sc = __ldg(&nsc[k0+kk]), sh = __ldg(&nsh[k0+kk]);
                    v.x = v.x*sc + sh; v.y = v.y*sc + sh;
                    v.z = v.z*sc + sh; v.w = v.w*sc + sh;
                }
                *(float4*)&As[kk][p4] = v;
            }
        } else {
            #pragma unroll
            for (int t = 0; t < 4; t++) {
                int f = tid + t*128;
                int mm = f >> 2; int q4 = (f & 3) << 2;
                float4 v = *(const float4*)(A + (size_t)(m0+mm)*K + k0 + q4);
                As[q4+0][mm] = v.x; As[q4+1][mm] = v.y;
                As[q4+2][mm] = v.z; As[q4+3][mm] = v.w;
            }
        }
        #pragma unroll
        for (int t = 0; t < NH*2; t++) {
            int f = tid + t*128;
            int nn = f >> 2; int q4 = (f & 3) << 2;
            float4 v = make_float4(0.f, 0.f, 0.f, 0.f);
            if (n0 + nn < N) v = *(const float4*)(Wt + (size_t)(n0+nn)*K + k0 + q4);
            Ws[q4+0][nn] = v.x; Ws[q4+1][nn] = v.y;
            Ws[q4+2][nn] = v.z; Ws[q4+3][nn] = v.w;
        }
        __syncthreads();
        #pragma unroll
        for (int kk = 0; kk < 16; kk++) {
            unsigned long long a2[8];
            #pragma unroll
            for (int g = 0; g < 4; g++) {
                a2[g*2+0] = *(const unsigned long long*)&As[kk][g*32 + tm*4];
                a2[g*2+1] = *(const unsigned long long*)&As[kk][g*32 + tm*4 + 2];
            }
            unsigned long long w2[NCOL];
            #pragma unroll
            for (int h = 0; h < NH; h++) {
                float4 wv = *(const float4*)&Ws[kk][h*64 + tn*4];
                w2[h*4+0] = packbc(wv.x); w2[h*4+1] = packbc(wv.y);
                w2[h*4+2] = packbc(wv.z); w2[h*4+3] = packbc(wv.w);
            }
            #pragma unroll
            for (int rp = 0; rp < 8; rp++)
                #pragma unroll
                for (int c = 0; c < NCOL; c++)
                    FMA2(acc2[rp][c], a2[rp], w2[c]);
        }
        __syncthreads();
    }

    if (OUT_NM) {
        #pragma unroll
        for (int h = 0; h < NH; h++)
            #pragma unroll
            for (int j = 0; j < 4; j++) {
                int c = h*4 + j;
                int n = n0 + h*64 + tn*4 + j;
                if (n >= N) continue;
                float bv = bias ? bias[n] : 0.f;
                float* cp = Co + (size_t)n*M + m0;
                #pragma unroll
                for (int g = 0; g < 4; g++) {
                    float2 lo = unpack2(acc2[g*2+0][c]);
                    float2 hi = unpack2(acc2[g*2+1][c]);
                    float4 v;
                    v.x = lo.x + bv; v.y = lo.y + bv;
                    v.z = hi.x + bv; v.w = hi.y + bv;
                    if (ACT == 1) {
                        v.x = geluf(v.x); v.y = geluf(v.y);
                        v.z = geluf(v.z); v.w = geluf(v.w);
                    }
                    float* dst = cp + g*32 + tm*4;
                    if (ACC) {
                        float4 o = *(float4*)dst;
                        v.x += o.x; v.y += o.y; v.z += o.z; v.w += o.w;
                    }
                    *(float4*)dst = v;
                }
            }
    } else {
        bool vec = ((N & 3) == 0);
        #pragma unroll
        for (int g = 0; g < 4; g++)
            #pragma unroll
            for (int p = 0; p < 2; p++)
                #pragma unroll
                for (int e = 0; e < 2; e++) {
                    int m = m0 + g*32 + tm*4 + p*2 + e;
                    float* rowp = Co + (size_t)m*N;
                    #pragma unroll
                    for (int h = 0; h < NH; h++) {
                        int nb = n0 + h*64 + tn*4;
                        float vv[4];
                        #pragma unroll
                        for (int j = 0; j < 4; j++) {
                            float2 uv = unpack2(acc2[g*2+p][h*4+j]);
                            float v = (e == 0) ? uv.x : uv.y;
                            if (nb + j < N) v += (bias ? bias[nb+j] : 0.f);
                            if (ACT == 1) v = geluf(v);
                            vv[j] = v;
                        }
                        if (vec && nb + 3 < N) {
                            float4 v4 = make_float4(vv[0], vv[1], vv[2], vv[3]);
                            if (ACC) {
                                float4 o = *(float4*)(rowp + nb);
                                v4.x += o.x; v4.y += o.y; v4.z += o.z; v4.w += o.w;
                            }
                            *(float4*)(rowp + nb) = v4;
                        } else {
                            #pragma unroll
                            for (int j = 0; j < 4; j++) {
                                if (nb + j < N) {
                                    float v = vv[j];
                                    if (ACC) v += rowp[nb+j];
                                    rowp[nb+j] = v;
                                }
                            }
                        }
                    }
                }
    }
}

// ---------------- LayerNorm over C with transpose ----------------
__global__ __launch_bounds__(256) void ln1_kernel(const float* __restrict__ x,
                                                  const float* __restrict__ g,
                                                  const float* __restrict__ bta) {
    __shared__ float s[96][33];
    __shared__ float mu_s[32], rs_s[32];
    int b = blockIdx.y;
    int l0 = blockIdx.x * 32;
    int tid = threadIdx.x;
    int tx = tid & 31, ty = tid >> 5;
    const float* xp = x + (size_t)b * C_ * L_;
    for (int c = ty; c < C_; c += 8)
        s[c][tx] = xp[(size_t)c * L_ + l0 + tx];
    __syncthreads();
    if (tid < 32) {
        float sum = 0.f, sq = 0.f;
        #pragma unroll 4
        for (int c = 0; c < C_; c++) { float v = s[c][tid]; sum += v; sq += v*v; }
        float mu = sum / 96.f;
        float var = sq / 96.f - mu*mu;
        mu_s[tid] = mu; rs_s[tid] = rsqrtf(var + 1e-5f);
    }
    __syncthreads();
    for (int idx = tid; idx < 96*32; idx += 256) {
        int c = idx % 96, l = idx / 96;
        float v = s[c][l];
        size_t row = (size_t)(b*L_ + l0 + l);
        g_xflat[row*96 + c] = v;
        g_xn[row*96 + c] = (v - mu_s[l]) * rs_s[l] * g[c] + bta[c];
    }
}

// ---------------- causal depthwise conv1d (k=4) + SiLU, channel-major streams ---------
__global__ __launch_bounds__(256) void conv1d_kernel(const float* __restrict__ w,
                                                     const float* __restrict__ bias) {
    int idx = blockIdx.x * 256 + threadIdx.x;       // (d*B + b, lb)
    int lb = idx % (L_/4);
    int db = idx / (L_/4);
    if (db >= DINNER * B_) return;
    int b = db % B_, d = db / B_;
    const float* xp = g_xzT + (size_t)d*NROWS + (size_t)b*L_;
    float4 v = *(const float4*)(xp + lb*4);
    float4 p = make_float4(0.f, 0.f, 0.f, 0.f);
    if (lb > 0) p = *(const float4*)(xp + lb*4 - 4);
    float w0 = w[d*4+0], w1 = w[d*4+1], w2 = w[d*4+2], w3 = w[d*4+3];
    float bv = bias[d];
    float4 o;
    o.x = bv + p.y*w0 + p.z*w1 + p.w*w2 + v.x*w3;
    o.y = bv + p.z*w0 + p.w*w1 + v.x*w2 + v.y*w3;
    o.z = bv + p.w*w0 + v.x*w1 + v.y*w2 + v.z*w3;
    o.w = bv + v.x*w0 + v.y*w1 + v.z*w2 + v.w*w3;
    o.x = siluf(o.x); o.y = siluf(o.y); o.z = siluf(o.z); o.w = siluf(o.w);
    *(float4*)(g_uT + (size_t)d*NROWS + (size_t)b*L_ + lb*4) = o;
}

// ---------------- dt = softplus(x_dbl[:, :6] @ dt_proj_w^T + b), transposed out -------
__global__ __launch_bounds__(256) void dt2_kernel(const float* __restrict__ dtw,
                                                  const float* __restrict__ dtb) {
    __shared__ float ws[DINNER*6];
    __shared__ float bs[DINNER];
    int tid = threadIdx.x;
    int r0 = blockIdx.x * 256;
    for (int i = tid; i < DINNER*6; i += 256) ws[i] = dtw[i];
    if (tid < DINNER) bs[tid] = dtb[tid];
    __syncthreads();
    float x0 = g_xdT[0*NROWS + r0 + tid];
    float x1 = g_xdT[1*NROWS + r0 + tid];
    float x2 = g_xdT[2*NROWS + r0 + tid];
    float x3 = g_xdT[3*NROWS + r0 + tid];
    float x4 = g_xdT[4*NROWS + r0 + tid];
    float x5 = g_xdT[5*NROWS + r0 + tid];
    for (int d = 0; d < DINNER; d++) {
        float acc = bs[d];
        acc += x0*ws[d*6+0]; acc += x1*ws[d*6+1]; acc += x2*ws[d*6+2];
        acc += x3*ws[d*6+3]; acc += x4*ws[d*6+4]; acc += x5*ws[d*6+5];
        float sp = (acc > 20.f) ? acc : log1pf(__expf(acc));
        g_dtT[(size_t)d*NROWS + r0 + tid] = sp;
    }
}

// ---------------- chunked selective scan (channel-major streams, float4) -------------
__global__ __launch_bounds__(128) void scan_phase1(const float* __restrict__ A_log) {
    int wid = (blockIdx.x * blockDim.x + threadIdx.x) >> 5;
    int lane = threadIdx.x & 31;
    int s = lane & 15, grp = lane >> 4;
    int pair = wid % 192;
    int chunk = wid / 192;
    int chan = pair*2 + grp;
    int b = chan / DINNER, d = chan % DINNER;
    float Aa = -expf(A_log[d*DSTATE + s]);
    float h = 0.f, P = 1.f;
    size_t base = (size_t)b*L_ + (size_t)chunk*CS;
    const float4* dtp = (const float4*)(g_dtT + (size_t)d*NROWS + base);
    const float4* up  = (const float4*)(g_uT  + (size_t)d*NROWS + base);
    const float4* bp  = (const float4*)(g_xdT + (size_t)(6+s)*NROWS + base);
    #pragma unroll 2
    for (int q = 0; q < CS/4; q++) {
        float4 dt4 = dtp[q], u4 = up[q], b4 = bp[q];
        float a;
        a = __expf(dt4.x*Aa); h = a*h + (dt4.x*u4.x)*b4.x; P *= a;
        a = __expf(dt4.y*Aa); h = a*h + (dt4.y*u4.y)*b4.y; P *= a;
        a = __expf(dt4.z*Aa); h = a*h + (dt4.z*u4.z)*b4.z; P *= a;
        a = __expf(dt4.w*Aa); h = a*h + (dt4.w*u4.w)*b4.w; P *= a;
    }
    int o = (chunk*384 + chan)*DSTATE + s;
    g_F[o] = h; g_P[o] = P;
}

__global__ __launch_bounds__(256) void scan_phase2() {
    int t = blockIdx.x * 256 + threadIdx.x;
    if (t >= 384*DSTATE) return;
    float H = 0.f;
    for (int j = 0; j < NC; j++) {
        int o = j*384*DSTATE + t;
        g_Hi[o] = H;
        H = g_F[o] + g_P[o]*H;
    }
}

__global__ __launch_bounds__(128) void scan_phase3(const float* __restrict__ A_log,
                                                   const float* __restrict__ Dp) {
    int wid = (blockIdx.x * blockDim.x + threadIdx.x) >> 5;
    int lane = threadIdx.x & 31;
    int s = lane & 15, grp = lane >> 4;
    int pair = wid % 192;
    int chunk = wid / 192;
    int chan = pair*2 + grp;
    int b = chan / DINNER, d = chan % DINNER;
    float Aa = -expf(A_log[d*DSTATE + s]);
    float Dpd = Dp[d];
    float h = g_Hi[(chunk*384 + chan)*DSTATE + s];
    size_t base = (size_t)b*L_ + (size_t)chunk*CS;
    const float4* dtp = (const float4*)(g_dtT + (size_t)d*NROWS + base);
    const float4* up  = (const float4*)(g_uT  + (size_t)d*NROWS + base);
    const float4* bp  = (const float4*)(g_xdT + (size_t)(6+s)*NROWS + base);
    const float4* cp  = (const float4*)(g_xdT + (size_t)(22+s)*NROWS + base);
    const float4* zp  = (const float4*)(g_xzT + (size_t)(192+d)*NROWS + base);
    float4* yp = (float4*)(g_yT + (size_t)d*NROWS + base);
    for (int q = 0; q < CS/4; q++) {
        float4 dt4 = dtp[q], u4 = up[q], b4 = bp[q], c4 = cp[q], z4 = zp[q];
        float4 yv;
        float a, p;
        a = __expf(dt4.x*Aa); h = a*h + (dt4.x*u4.x)*b4.x;
        p = h * c4.x;
        p += __shfl_xor_sync(0xffffffffu, p, 8);
        p += __shfl_xor_sync(0xffffffffu, p, 4);
        p += __shfl_xor_sync(0xffffffffu, p, 2);
        p += __shfl_xor_sync(0xffffffffu, p, 1);
        yv.x = (p + u4.x*Dpd) * siluf(z4.x);
        a = __expf(dt4.y*Aa); h = a*h + (dt4.y*u4.y)*b4.y;
        p = h * c4.y;
        p += __shfl_xor_sync(0xffffffffu, p, 8);
        p += __shfl_xor_sync(0xffffffffu, p, 4);
        p += __shfl_xor_sync(0xffffffffu, p, 2);
        p += __shfl_xor_sync(0xffffffffu, p, 1);
        yv.y = (p + u4.y*Dpd) * siluf(z4.y);
        a = __expf(dt4.z*Aa); h = a*h + (dt4.z*u4.z)*b4.z;
        p = h * c4.z;
        p += __shfl_xor_sync(0xffffffffu, p, 8);
        p += __shfl_xor_sync(0xffffffffu, p, 4);
        p += __shfl_xor_sync(0xffffffffu, p, 2);
        p += __shfl_xor_sync(0xffffffffu, p, 1);
        yv.z = (p + u4.z*Dpd) * siluf(z4.z);
        a = __expf(dt4.w*Aa); h = a*h + (dt4.w*u4.w)*b4.w;
        p = h * c4.w;
        p += __shfl_xor_sync(0xffffffffu, p, 8);
        p += __shfl_xor_sync(0xffffffffu, p, 4);
        p += __shfl_xor_sync(0xffffffffu, p, 2);
        p += __shfl_xor_sync(0xffffffffu, p, 1);
        yv.w = (p + u4.w*Dpd) * siluf(z4.w);
        if (s == 0) yp[q] = yv;
    }
}

// ---------------- residual + LayerNorm (warp per row) ----------------
__global__ __launch_bounds__(256) void ln2_kernel(const float* __restrict__ g,
                                                  const float* __restrict__ bta,
                                                  const float* __restrict__ skip) {
    int warp = (int)((blockIdx.x * blockDim.x + threadIdx.x) >> 5);
    int lane = threadIdx.x & 31;
    if (warp >= NROWS) return;
    float sk = skip[0];
    size_t base = (size_t)warp * 96;
    float t[3]; float sum = 0.f, sq = 0.f;
    #pragma unroll
    for (int i = 0; i < 3; i++) {
        int c = lane + 32*i;
        t[i] = g_outm[base+c] + sk * g_xflat[base+c];
        sum += t[i]; sq += t[i]*t[i];
    }
    #pragma unroll
    for (int k = 16; k > 0; k >>= 1) {
        sum += __shfl_xor_sync(0xffffffffu, sum, k);
        sq  += __shfl_xor_sync(0xffffffffu, sq,  k);
    }
    float mu = sum / 96.f;
    float var = sq / 96.f - mu*mu;
    float inv = rsqrtf(var + 1e-5f);
    #pragma unroll
    for (int i = 0; i < 3; i++) {
        int c = lane + 32*i;
        g_xm2[base+c] = (t[i] - mu) * inv * g[c] + bta[c];
    }
}

// ---------------- launch ----------------
extern "C" void kernel_launch(void* const* d_in, const int* in_sizes, int n_in,
                              void* d_out, int out_size) {
    const float* x     = (const float*)d_in[0];
    const float* dw_w  = (const float*)d_in[1];
    const float* dw_b  = (const float*)d_in[2];
    const float* gn_g  = (const float*)d_in[3];
    const float* gn_b  = (const float*)d_in[4];
    const float* pw1_w = (const float*)d_in[5];
    const float* pw1_b = (const float*)d_in[6];
    const float* pw2_w = (const float*)d_in[7];
    const float* pw2_b = (const float*)d_in[8];
    const float* ln_g  = (const float*)d_in[9];
    const float* ln_b  = (const float*)d_in[10];
    const float* skip  = (const float*)d_in[11];
    const float* inpw  = (const float*)d_in[12];
    const float* c1w   = (const float*)d_in[13];
    const float* c1b   = (const float*)d_in[14];
    const float* xpw   = (const float*)d_in[15];
    const float* dtw   = (const float*)d_in[16];
    const float* dtb   = (const float*)d_in[17];
    const float* A_log = (const float*)d_in[18];
    const float* Dp    = (const float*)d_in[19];
    const float* outpw = (const float*)d_in[20];
    const float* projw = (const float*)d_in[21];
    const float* projb = (const float*)d_in[22];
    float* out = (float*)d_out;

    float *p_h1, *p_h2, *p_xn, *p_xzT, *p_uT, *p_xdT, *p_yT, *p_outm, *p_xm2, *p_sc, *p_sh;
    cudaGetSymbolAddress((void**)&p_h1,   g_h1);
    cudaGetSymbolAddress((void**)&p_h2,   g_h2);
    cudaGetSymbolAddress((void**)&p_xn,   g_xn);
    cudaGetSymbolAddress((void**)&p_xzT,  g_xzT);
    cudaGetSymbolAddress((void**)&p_uT,   g_uT);
    cudaGetSymbolAddress((void**)&p_xdT,  g_xdT);
    cudaGetSymbolAddress((void**)&p_yT,   g_yT);
    cudaGetSymbolAddress((void**)&p_outm, g_outm);
    cudaGetSymbolAddress((void**)&p_xm2,  g_xm2);
    cudaGetSymbolAddress((void**)&p_sc,   g_gnsc);
    cudaGetSymbolAddress((void**)&p_sh,   g_gnsh);

    // ---- conv branch ----
    zero_stats_kernel<<<1,32>>>();
    dwconv3d_kernel<<<dim3(3,3,B_*C_), dim3(16,16)>>>(x, dw_w, dw_b);
    gn_scale_kernel<<<1,256>>>(gn_g, gn_b);
    // pw1 with fused GN on A-load: h2(b,o,l) = gelu(W1 @ gn(h1))
    gemm2_kernel<true,true,1,false,128,true><<<dim3(L_/128, 3, B_),128>>>(
        p_h1, pw1_w, pw1_b, p_h2, L_, 4*C_, C_, (size_t)C_*L_, (size_t)4*C_*L_, p_sc, p_sh);
    // pw2: conv_out directly into d_out
    gemm2_kernel<true,true,0,false,128,false><<<dim3(L_/128, 1, B_),128>>>(
        p_h2, pw2_w, pw2_b, out, L_, C_, 4*C_, (size_t)4*C_*L_, (size_t)C_*L_, nullptr, nullptr);

    // ---- mamba branch ----
    ln1_kernel<<<dim3(L_/32, B_),256>>>(x, ln_g, ln_b);
    // in_proj: transposed output -> g_xzT [384][NROWS]
    gemm2_kernel<false,true,0,false,128,false><<<dim3(NROWS/128, 3, 1),128>>>(
        p_xn, inpw, nullptr, p_xzT, NROWS, 2*DINNER, C_, 0, 0, nullptr, nullptr);
    conv1d_kernel<<<(DINNER*B_*(L_/4))/256,256>>>(c1w, c1b);
    // x_proj: A = uT (K-major), transposed output -> g_xdT [38][NROWS]
    gemm2_kernel<true,true,0,false,64,false><<<dim3(NROWS/128, 1, 1),128>>>(
        p_uT, xpw, nullptr, p_xdT, NROWS, 38, DINNER, 0, 0, nullptr, nullptr);
    dt2_kernel<<<NROWS/256,256>>>(dtw, dtb);
    scan_phase1<<<(192*NC)/4, 128>>>(A_log);
    scan_phase2<<<24,256>>>();
    scan_phase3<<<(192*NC)/4, 128>>>(A_log, Dp);
    // out_proj: A = yT (K-major), row-major out
    gemm2_kernel<true,false,0,false,128,false><<<dim3(NROWS/128, 1, 1),128>>>(
        p_yT, outpw, nullptr, p_outm, NROWS, C_, DINNER, 0, 0, nullptr, nullptr);
    ln2_kernel<<<NROWS/8,256>>>(ln_g, ln_b, skip);
    // final proj, transposed write, accumulate onto conv_out in d_out
    gemm2_kernel<false,true,0,true,128,false><<<dim3(L_/128, 1, B_),128>>>(
        p_xm2, projw, projb, out, L_, C_, C_, (size_t)L_*C_, (size_t)C_*L_, nullptr, nullptr);
}